// round 3
// baseline (speedup 1.0000x reference)
#include <cuda_runtime.h>
#include <math.h>

// Problem shape (fixed by the reference's setup_inputs)
#define Bn 4
#define Tn 8192
#define Dn 1024
#define D4n (Dn / 4)   // 256 float4 groups across channel dim
#define Ln 32          // chunk length along time
#define Cn (Tn / Ln)   // 256 chunks
#define CPL 8          // chunks per lane in pass2 (Cn / 32)

// Per-channel recurrence multiplier r = exp(-|a|) * (cos f + i sin f)
__device__ float2 g_r[Dn];

// Scratch: chunk-end states and chunk carry-in states, complex fp32.
// Layout: [c][b][k][d4], k = sub-lane within the float4 group. 8 MB each.
__device__ float2 g_ends [Cn * Bn * 4 * D4n];
__device__ float2 g_carry[Cn * Bn * 4 * D4n];

// ---------------------------------------------------------------------------
// setup: compute r per channel
// ---------------------------------------------------------------------------
__global__ void k_setup(const float* __restrict__ decay,
                        const float* __restrict__ freq)
{
    int d = blockIdx.x * blockDim.x + threadIdx.x;
    if (d >= Dn) return;
    float g = expf(-fabsf(decay[d]));
    float s, co;
    sincosf(freq[d], &s, &co);
    g_r[d] = make_float2(g * co, g * s);
}

// ---------------------------------------------------------------------------
// pass1: local recurrence per chunk, zero initial state; emit chunk-end z.
// ---------------------------------------------------------------------------
__global__ __launch_bounds__(256)
void k_pass1(const float4* __restrict__ x)
{
    int tid = blockIdx.x * blockDim.x + threadIdx.x;
    int d4 = tid % D4n;
    int b  = (tid / D4n) % Bn;
    int c  = tid / (D4n * Bn);

    const float4* rp = (const float4*)g_r;
    float4 r01 = rp[2 * d4 + 0];
    float4 r23 = rp[2 * d4 + 1];
    float rre[4] = {r01.x, r01.z, r23.x, r23.z};
    float rim[4] = {r01.y, r01.w, r23.y, r23.w};
    float zre[4] = {0.f, 0.f, 0.f, 0.f};
    float zim[4] = {0.f, 0.f, 0.f, 0.f};

    const float4* xp = x + (size_t)(b * Tn + c * Ln) * D4n + d4;
#pragma unroll 8
    for (int j = 0; j < Ln; j++) {
        float4 xv = xp[(size_t)j * D4n];
        float xr[4] = {xv.x, xv.y, xv.z, xv.w};
#pragma unroll
        for (int k = 0; k < 4; k++) {
            float nre = fmaf(rre[k], zre[k], fmaf(-rim[k], zim[k], xr[k]));
            float nim = fmaf(rre[k], zim[k], rim[k] * zre[k]);
            zre[k] = nre;
            zim[k] = nim;
        }
    }

#pragma unroll
    for (int k = 0; k < 4; k++)
        g_ends[((c * Bn + b) * 4 + k) * D4n + d4] = make_float2(zre[k], zim[k]);
}

// ---------------------------------------------------------------------------
// pass2: warp-parallel weighted scan across chunks. One warp per (b,d)
// series. Lane l owns chunks [8l, 8l+8). All scan weights r^(L*n) come from
// the double-precision closed form (no rounding accumulation).
// ---------------------------------------------------------------------------
__global__ __launch_bounds__(256)
void k_pass2(const float* __restrict__ decay,
             const float* __restrict__ freq)
{
    int gtid = blockIdx.x * blockDim.x + threadIdx.x;
    int wid  = gtid >> 5;            // 0 .. Bn*Dn-1
    int lane = gtid & 31;
    if (wid >= Bn * Dn) return;
    int d = wid % Dn;
    int b = wid / Dn;
    int d4 = d >> 2;
    int k  = d & 3;

    double a = fabs((double)decay[d]);
    double f = (double)freq[d];

    // r^L (per-chunk multiplier), closed form
    double glL = exp(-a * (double)Ln);
    float rLre = (float)(glL * cos(f * (double)Ln));
    float rLim = (float)(glL * sin(f * (double)Ln));

    // Load this lane's 8 chunk-ends, combine into group aggregate:
    // A = sum_i e_i * rL^(7-i)
    float2 e[CPL];
    float Are = 0.0f, Aim = 0.0f;
#pragma unroll
    for (int i = 0; i < CPL; i++) {
        int c = lane * CPL + i;
        e[i] = g_ends[((c * Bn + b) * 4 + k) * D4n + d4];
        float nre = fmaf(rLre, Are, fmaf(-rLim, Aim, e[i].x));
        float nim = fmaf(rLre, Aim, fmaf(rLim, Are, e[i].y));
        Are = nre; Aim = nim;
    }

    // Kogge-Stone inclusive scan across lanes with weight m8 = r^(8L):
    // S_l <- S_l + m8^off * S_{l-off}
    float Sre = Are, Sim = Aim;
#pragma unroll
    for (int step = 0; step < 5; step++) {
        int off = 1 << step;
        double span = (double)(CPL * Ln * off);     // L * 8 * off
        double gw = exp(-a * span);
        float Wre = (float)(gw * cos(f * span));
        float Wim = (float)(gw * sin(f * span));
        float Pre = __shfl_up_sync(0xFFFFFFFFu, Sre, off);
        float Pim = __shfl_up_sync(0xFFFFFFFFu, Sim, off);
        if (lane >= off) {
            Sre = fmaf(Wre, Pre, fmaf(-Wim, Pim, Sre));
            Sim = fmaf(Wre, Pim, fmaf(Wim, Pre, Sim));
        }
    }

    // Exclusive group carry for this lane = inclusive of lane-1
    float Cre = __shfl_up_sync(0xFFFFFFFFu, Sre, 1);
    float Cim = __shfl_up_sync(0xFFFFFFFFu, Sim, 1);
    if (lane == 0) { Cre = 0.0f; Cim = 0.0f; }

    // Replay lane's chunks, writing per-chunk carry-in.
#pragma unroll
    for (int i = 0; i < CPL; i++) {
        int c = lane * CPL + i;
        g_carry[((c * Bn + b) * 4 + k) * D4n + d4] = make_float2(Cre, Cim);
        float nre = fmaf(rLre, Cre, fmaf(-rLim, Cim, e[i].x));
        float nim = fmaf(rLre, Cim, fmaf(rLim, Cre, e[i].y));
        Cre = nre; Cim = nim;
    }
}

// ---------------------------------------------------------------------------
// pass3: rerun local recurrence seeded with carry-in; write y = Re(z).
// ---------------------------------------------------------------------------
__global__ __launch_bounds__(256)
void k_pass3(const float4* __restrict__ x,
             float4* __restrict__ y)
{
    int tid = blockIdx.x * blockDim.x + threadIdx.x;
    int d4 = tid % D4n;
    int b  = (tid / D4n) % Bn;
    int c  = tid / (D4n * Bn);

    const float4* rp = (const float4*)g_r;
    float4 r01 = rp[2 * d4 + 0];
    float4 r23 = rp[2 * d4 + 1];
    float rre[4] = {r01.x, r01.z, r23.x, r23.z};
    float rim[4] = {r01.y, r01.w, r23.y, r23.w};

    float zre[4], zim[4];
#pragma unroll
    for (int k = 0; k < 4; k++) {
        float2 cc = g_carry[((c * Bn + b) * 4 + k) * D4n + d4];
        zre[k] = cc.x;
        zim[k] = cc.y;
    }

    const float4* xp = x + (size_t)(b * Tn + c * Ln) * D4n + d4;
    float4*       yp = y + (size_t)(b * Tn + c * Ln) * D4n + d4;
#pragma unroll 8
    for (int j = 0; j < Ln; j++) {
        float4 xv = xp[(size_t)j * D4n];
        float xr[4] = {xv.x, xv.y, xv.z, xv.w};
#pragma unroll
        for (int k = 0; k < 4; k++) {
            float nre = fmaf(rre[k], zre[k], fmaf(-rim[k], zim[k], xr[k]));
            float nim = fmaf(rre[k], zim[k], rim[k] * zre[k]);
            zre[k] = nre;
            zim[k] = nim;
        }
        yp[(size_t)j * D4n] = make_float4(zre[0], zre[1], zre[2], zre[3]);
    }
}

// ---------------------------------------------------------------------------
extern "C" void kernel_launch(void* const* d_in, const int* in_sizes, int n_in,
                              void* d_out, int out_size)
{
    const float* x     = (const float*)d_in[0];
    const float* decay = (const float*)d_in[1];
    const float* freq  = (const float*)d_in[2];
    float* y = (float*)d_out;

    const int n1 = Cn * Bn * D4n;          // 262144 threads
    const int n2 = Bn * Dn * 32;           // 131072 threads (one warp/series)

    k_setup<<<(Dn + 255) / 256, 256>>>(decay, freq);
    k_pass1<<<n1 / 256, 256>>>((const float4*)x);
    k_pass2<<<n2 / 256, 256>>>(decay, freq);
    k_pass3<<<n1 / 256, 256>>>((const float4*)x, (float4*)y);
}

// round 4
// speedup vs baseline: 1.5962x; 1.5962x over previous
#include <cuda_runtime.h>
#include <math.h>

// Problem shape (fixed by the reference's setup_inputs)
#define Bn 4
#define Tn 8192
#define Dn 1024
#define D4n (Dn / 4)   // 256 float4 groups across channel dim
#define Ln 32          // chunk length along time
#define Cn (Tn / Ln)   // 256 chunks
#define CPL 8          // chunks per lane in pass2 (Cn / 32)

// Per-channel tables (precomputed in k_setup from double closed form):
//   g_r  : r        = exp(-|a|) (cos f, sin f)        [pass1/pass3 step]
//   g_rL : r^L                                        [pass2 serial combine]
//   g_w  : r^(8L * 2^s), s = 0..4                     [pass2 shuffle scan]
__device__ float2 g_r [Dn];
__device__ float2 g_rL[Dn];
__device__ float2 g_w [5][Dn];

// Scratch: chunk-end states and chunk carry-in states, complex fp32.
// Layout: [c][b][k][d4], k = sub-lane within the float4 group. 8 MB each.
__device__ float2 g_ends [Cn * Bn * 4 * D4n];
__device__ float2 g_carry[Cn * Bn * 4 * D4n];

// ---------------------------------------------------------------------------
// setup: all double-precision closed-form math lives here (1024 threads).
// ---------------------------------------------------------------------------
__global__ void k_setup(const float* __restrict__ decay,
                        const float* __restrict__ freq)
{
    int d = blockIdx.x * blockDim.x + threadIdx.x;
    if (d >= Dn) return;
    double a = fabs((double)decay[d]);
    double f = (double)freq[d];

    double g1 = exp(-a);
    g_r[d] = make_float2((float)(g1 * cos(f)), (float)(g1 * sin(f)));

    double gL = exp(-a * (double)Ln);
    g_rL[d] = make_float2((float)(gL * cos(f * (double)Ln)),
                          (float)(gL * sin(f * (double)Ln)));

#pragma unroll
    for (int s = 0; s < 5; s++) {
        double span = (double)(CPL * Ln * (1 << s));
        double gw = exp(-a * span);
        g_w[s][d] = make_float2((float)(gw * cos(f * span)),
                                (float)(gw * sin(f * span)));
    }
}

// ---------------------------------------------------------------------------
// pass1: local recurrence per chunk, zero initial state; emit chunk-end z.
// ---------------------------------------------------------------------------
__global__ __launch_bounds__(256)
void k_pass1(const float4* __restrict__ x)
{
    int tid = blockIdx.x * blockDim.x + threadIdx.x;
    int d4 = tid % D4n;
    int b  = (tid / D4n) % Bn;
    int c  = tid / (D4n * Bn);

    const float4* rp = (const float4*)g_r;
    float4 r01 = rp[2 * d4 + 0];
    float4 r23 = rp[2 * d4 + 1];
    float rre[4] = {r01.x, r01.z, r23.x, r23.z};
    float rim[4] = {r01.y, r01.w, r23.y, r23.w};
    float zre[4] = {0.f, 0.f, 0.f, 0.f};
    float zim[4] = {0.f, 0.f, 0.f, 0.f};

    const float4* xp = x + (size_t)(b * Tn + c * Ln) * D4n + d4;
#pragma unroll 8
    for (int j = 0; j < Ln; j++) {
        float4 xv = xp[(size_t)j * D4n];
        float xr[4] = {xv.x, xv.y, xv.z, xv.w};
#pragma unroll
        for (int k = 0; k < 4; k++) {
            float nre = fmaf(rre[k], zre[k], fmaf(-rim[k], zim[k], xr[k]));
            float nim = fmaf(rre[k], zim[k], rim[k] * zre[k]);
            zre[k] = nre;
            zim[k] = nim;
        }
    }

#pragma unroll
    for (int k = 0; k < 4; k++)
        g_ends[((c * Bn + b) * 4 + k) * D4n + d4] = make_float2(zre[k], zim[k]);
}

// ---------------------------------------------------------------------------
// pass2: warp-parallel weighted scan across chunks, pure fp32.
// One warp per (b,d) series; lane l owns chunks [8l, 8l+8).
// ---------------------------------------------------------------------------
__global__ __launch_bounds__(256)
void k_pass2()
{
    int gtid = blockIdx.x * blockDim.x + threadIdx.x;
    int wid  = gtid >> 5;            // 0 .. Bn*Dn-1
    int lane = gtid & 31;
    int d = wid % Dn;
    int b = wid / Dn;
    int d4 = d >> 2;
    int k  = d & 3;

    float2 rL = g_rL[d];
    float rLre = rL.x, rLim = rL.y;

    // Serial combine over this lane's 8 chunk-ends: A = sum_i e_i * rL^(7-i)
    float2 e[CPL];
    float Are = 0.0f, Aim = 0.0f;
#pragma unroll
    for (int i = 0; i < CPL; i++) {
        int c = lane * CPL + i;
        e[i] = g_ends[((c * Bn + b) * 4 + k) * D4n + d4];
        float nre = fmaf(rLre, Are, fmaf(-rLim, Aim, e[i].x));
        float nim = fmaf(rLre, Aim, fmaf(rLim, Are, e[i].y));
        Are = nre; Aim = nim;
    }

    // Kogge-Stone inclusive scan with precomputed span weights.
    float Sre = Are, Sim = Aim;
#pragma unroll
    for (int step = 0; step < 5; step++) {
        int off = 1 << step;
        float2 w = g_w[step][d];
        float Pre = __shfl_up_sync(0xFFFFFFFFu, Sre, off);
        float Pim = __shfl_up_sync(0xFFFFFFFFu, Sim, off);
        if (lane >= off) {
            Sre = fmaf(w.x, Pre, fmaf(-w.y, Pim, Sre));
            Sim = fmaf(w.x, Pim, fmaf(w.y, Pre, Sim));
        }
    }

    // Exclusive group carry for this lane = inclusive of lane-1
    float Cre = __shfl_up_sync(0xFFFFFFFFu, Sre, 1);
    float Cim = __shfl_up_sync(0xFFFFFFFFu, Sim, 1);
    if (lane == 0) { Cre = 0.0f; Cim = 0.0f; }

    // Replay lane's chunks, writing per-chunk carry-in.
#pragma unroll
    for (int i = 0; i < CPL; i++) {
        int c = lane * CPL + i;
        g_carry[((c * Bn + b) * 4 + k) * D4n + d4] = make_float2(Cre, Cim);
        float nre = fmaf(rLre, Cre, fmaf(-rLim, Cim, e[i].x));
        float nim = fmaf(rLre, Cim, fmaf(rLim, Cre, e[i].y));
        Cre = nre; Cim = nim;
    }
}

// ---------------------------------------------------------------------------
// pass3: rerun local recurrence seeded with carry-in; write y = Re(z).
// ---------------------------------------------------------------------------
__global__ __launch_bounds__(256)
void k_pass3(const float4* __restrict__ x,
             float4* __restrict__ y)
{
    int tid = blockIdx.x * blockDim.x + threadIdx.x;
    int d4 = tid % D4n;
    int b  = (tid / D4n) % Bn;
    int c  = tid / (D4n * Bn);

    const float4* rp = (const float4*)g_r;
    float4 r01 = rp[2 * d4 + 0];
    float4 r23 = rp[2 * d4 + 1];
    float rre[4] = {r01.x, r01.z, r23.x, r23.z};
    float rim[4] = {r01.y, r01.w, r23.y, r23.w};

    float zre[4], zim[4];
#pragma unroll
    for (int k = 0; k < 4; k++) {
        float2 cc = g_carry[((c * Bn + b) * 4 + k) * D4n + d4];
        zre[k] = cc.x;
        zim[k] = cc.y;
    }

    const float4* xp = x + (size_t)(b * Tn + c * Ln) * D4n + d4;
    float4*       yp = y + (size_t)(b * Tn + c * Ln) * D4n + d4;
#pragma unroll 8
    for (int j = 0; j < Ln; j++) {
        float4 xv = xp[(size_t)j * D4n];
        float xr[4] = {xv.x, xv.y, xv.z, xv.w};
#pragma unroll
        for (int k = 0; k < 4; k++) {
            float nre = fmaf(rre[k], zre[k], fmaf(-rim[k], zim[k], xr[k]));
            float nim = fmaf(rre[k], zim[k], rim[k] * zre[k]);
            zre[k] = nre;
            zim[k] = nim;
        }
        yp[(size_t)j * D4n] = make_float4(zre[0], zre[1], zre[2], zre[3]);
    }
}

// ---------------------------------------------------------------------------
extern "C" void kernel_launch(void* const* d_in, const int* in_sizes, int n_in,
                              void* d_out, int out_size)
{
    const float* x     = (const float*)d_in[0];
    const float* decay = (const float*)d_in[1];
    const float* freq  = (const float*)d_in[2];
    float* y = (float*)d_out;

    const int n1 = Cn * Bn * D4n;          // 262144 threads
    const int n2 = Bn * Dn * 32;           // 131072 threads (one warp/series)

    k_setup<<<(Dn + 255) / 256, 256>>>(decay, freq);
    k_pass1<<<n1 / 256, 256>>>((const float4*)x);
    k_pass2<<<n2 / 256, 256>>>();
    k_pass3<<<n1 / 256, 256>>>((const float4*)x, (float4*)y);
}

// round 5
// speedup vs baseline: 2.0572x; 1.2888x over previous
#include <cuda_runtime.h>
#include <math.h>

// Problem shape (fixed by the reference's setup_inputs)
#define Bn 4
#define Tn 8192
#define Dn 1024
#define D4n (Dn / 4)   // 256 float4 groups across channel dim
#define Ln 32          // chunk length along time
#define Cn (Tn / Ln)   // 256 chunks
#define CPL 8          // chunks per lane in pass2 (Cn / 32)

// Per-channel tables (precomputed in k_setup from double closed form):
//   g_r  : r        = exp(-|a|) (cos f, sin f)        [pass1/pass3 step]
//   g_rL : r^L                                        [pass2 serial combine]
//   g_w  : r^(8L * 2^s), s = 0..4                     [pass2 shuffle scan]
__device__ float2 g_r [Dn];
__device__ float2 g_rL[Dn];
__device__ float2 g_w [5][Dn];

// Scratch: chunk-end states and chunk carry-in states, complex fp32.
// Layout: [c][b][k][d4], k = sub-lane within the float4 group. 8 MB each.
__device__ float2 g_ends [Cn * Bn * 4 * D4n];
__device__ float2 g_carry[Cn * Bn * 4 * D4n];

// ---------------------------------------------------------------------------
// setup: one (exp, cos, sin) double triple PER THREAD — 7168 threads across
// 28 blocks, instead of 21 triples/thread on 4 blocks (which cost ~15-20us).
// job j: 0 -> g_r (span 1), 1 -> g_rL (span L), 2..6 -> g_w[j-2] (span 8L*2^(j-2))
// ---------------------------------------------------------------------------
__global__ void k_setup(const float* __restrict__ decay,
                        const float* __restrict__ freq)
{
    int tid = blockIdx.x * blockDim.x + threadIdx.x;
    if (tid >= 7 * Dn) return;
    int d = tid % Dn;
    int j = tid / Dn;

    double span;
    if (j == 0)      span = 1.0;
    else if (j == 1) span = (double)Ln;
    else             span = (double)(CPL * Ln * (1 << (j - 2)));

    double a = fabs((double)decay[d]);
    double f = (double)freq[d];
    double g = exp(-a * span);
    float2 v = make_float2((float)(g * cos(f * span)),
                           (float)(g * sin(f * span)));

    if (j == 0)      g_r[d]      = v;
    else if (j == 1) g_rL[d]     = v;
    else             g_w[j-2][d] = v;
}

// ---------------------------------------------------------------------------
// pass1: local recurrence per chunk, zero initial state; emit chunk-end z.
// ---------------------------------------------------------------------------
__global__ __launch_bounds__(256)
void k_pass1(const float4* __restrict__ x)
{
    int tid = blockIdx.x * blockDim.x + threadIdx.x;
    int d4 = tid % D4n;
    int b  = (tid / D4n) % Bn;
    int c  = tid / (D4n * Bn);

    const float4* rp = (const float4*)g_r;
    float4 r01 = rp[2 * d4 + 0];
    float4 r23 = rp[2 * d4 + 1];
    float rre[4] = {r01.x, r01.z, r23.x, r23.z};
    float rim[4] = {r01.y, r01.w, r23.y, r23.w};
    float zre[4] = {0.f, 0.f, 0.f, 0.f};
    float zim[4] = {0.f, 0.f, 0.f, 0.f};

    const float4* xp = x + (size_t)(b * Tn + c * Ln) * D4n + d4;
#pragma unroll 8
    for (int j = 0; j < Ln; j++) {
        float4 xv = xp[(size_t)j * D4n];
        float xr[4] = {xv.x, xv.y, xv.z, xv.w};
#pragma unroll
        for (int k = 0; k < 4; k++) {
            float nre = fmaf(rre[k], zre[k], fmaf(-rim[k], zim[k], xr[k]));
            float nim = fmaf(rre[k], zim[k], rim[k] * zre[k]);
            zre[k] = nre;
            zim[k] = nim;
        }
    }

#pragma unroll
    for (int k = 0; k < 4; k++)
        g_ends[((c * Bn + b) * 4 + k) * D4n + d4] = make_float2(zre[k], zim[k]);
}

// ---------------------------------------------------------------------------
// pass2: warp-parallel weighted scan across chunks, pure fp32.
// One warp per (b,d) series; lane l owns chunks [8l, 8l+8).
// ---------------------------------------------------------------------------
__global__ __launch_bounds__(256)
void k_pass2()
{
    int gtid = blockIdx.x * blockDim.x + threadIdx.x;
    int wid  = gtid >> 5;            // 0 .. Bn*Dn-1
    int lane = gtid & 31;
    int d = wid % Dn;
    int b = wid / Dn;
    int d4 = d >> 2;
    int k  = d & 3;

    float2 rL = g_rL[d];
    float rLre = rL.x, rLim = rL.y;

    // Serial combine over this lane's 8 chunk-ends: A = sum_i e_i * rL^(7-i)
    float2 e[CPL];
    float Are = 0.0f, Aim = 0.0f;
#pragma unroll
    for (int i = 0; i < CPL; i++) {
        int c = lane * CPL + i;
        e[i] = g_ends[((c * Bn + b) * 4 + k) * D4n + d4];
        float nre = fmaf(rLre, Are, fmaf(-rLim, Aim, e[i].x));
        float nim = fmaf(rLre, Aim, fmaf(rLim, Are, e[i].y));
        Are = nre; Aim = nim;
    }

    // Kogge-Stone inclusive scan with precomputed span weights.
    float Sre = Are, Sim = Aim;
#pragma unroll
    for (int step = 0; step < 5; step++) {
        int off = 1 << step;
        float2 w = g_w[step][d];
        float Pre = __shfl_up_sync(0xFFFFFFFFu, Sre, off);
        float Pim = __shfl_up_sync(0xFFFFFFFFu, Sim, off);
        if (lane >= off) {
            Sre = fmaf(w.x, Pre, fmaf(-w.y, Pim, Sre));
            Sim = fmaf(w.x, Pim, fmaf(w.y, Pre, Sim));
        }
    }

    // Exclusive group carry for this lane = inclusive of lane-1
    float Cre = __shfl_up_sync(0xFFFFFFFFu, Sre, 1);
    float Cim = __shfl_up_sync(0xFFFFFFFFu, Sim, 1);
    if (lane == 0) { Cre = 0.0f; Cim = 0.0f; }

    // Replay lane's chunks, writing per-chunk carry-in.
#pragma unroll
    for (int i = 0; i < CPL; i++) {
        int c = lane * CPL + i;
        g_carry[((c * Bn + b) * 4 + k) * D4n + d4] = make_float2(Cre, Cim);
        float nre = fmaf(rLre, Cre, fmaf(-rLim, Cim, e[i].x));
        float nim = fmaf(rLre, Cim, fmaf(rLim, Cre, e[i].y));
        Cre = nre; Cim = nim;
    }
}

// ---------------------------------------------------------------------------
// pass3: rerun local recurrence seeded with carry-in; write y = Re(z).
// ---------------------------------------------------------------------------
__global__ __launch_bounds__(256)
void k_pass3(const float4* __restrict__ x,
             float4* __restrict__ y)
{
    int tid = blockIdx.x * blockDim.x + threadIdx.x;
    int d4 = tid % D4n;
    int b  = (tid / D4n) % Bn;
    int c  = tid / (D4n * Bn);

    const float4* rp = (const float4*)g_r;
    float4 r01 = rp[2 * d4 + 0];
    float4 r23 = rp[2 * d4 + 1];
    float rre[4] = {r01.x, r01.z, r23.x, r23.z};
    float rim[4] = {r01.y, r01.w, r23.y, r23.w};

    float zre[4], zim[4];
#pragma unroll
    for (int k = 0; k < 4; k++) {
        float2 cc = g_carry[((c * Bn + b) * 4 + k) * D4n + d4];
        zre[k] = cc.x;
        zim[k] = cc.y;
    }

    const float4* xp = x + (size_t)(b * Tn + c * Ln) * D4n + d4;
    float4*       yp = y + (size_t)(b * Tn + c * Ln) * D4n + d4;
#pragma unroll 8
    for (int j = 0; j < Ln; j++) {
        float4 xv = xp[(size_t)j * D4n];
        float xr[4] = {xv.x, xv.y, xv.z, xv.w};
#pragma unroll
        for (int k = 0; k < 4; k++) {
            float nre = fmaf(rre[k], zre[k], fmaf(-rim[k], zim[k], xr[k]));
            float nim = fmaf(rre[k], zim[k], rim[k] * zre[k]);
            zre[k] = nre;
            zim[k] = nim;
        }
        yp[(size_t)j * D4n] = make_float4(zre[0], zre[1], zre[2], zre[3]);
    }
}

// ---------------------------------------------------------------------------
extern "C" void kernel_launch(void* const* d_in, const int* in_sizes, int n_in,
                              void* d_out, int out_size)
{
    const float* x     = (const float*)d_in[0];
    const float* decay = (const float*)d_in[1];
    const float* freq  = (const float*)d_in[2];
    float* y = (float*)d_out;

    const int n1 = Cn * Bn * D4n;          // 262144 threads
    const int n2 = Bn * Dn * 32;           // 131072 threads (one warp/series)
    const int ns = 7 * Dn;                 // 7168 setup jobs

    k_setup<<<(ns + 255) / 256, 256>>>(decay, freq);
    k_pass1<<<n1 / 256, 256>>>((const float4*)x);
    k_pass2<<<n2 / 256, 256>>>();
    k_pass3<<<n1 / 256, 256>>>((const float4*)x, (float4*)y);
}